// round 1
// baseline (speedup 1.0000x reference)
#include <cuda_runtime.h>
#include <cuda_bf16.h>
#include <math.h>

// ---------------------------------------------------------------------------
// Problem constants (shapes fixed by the dataset)
// ---------------------------------------------------------------------------
#define L     4096
#define HID   2560
#define NH    8          // query heads
#define NKV   4          // kv heads
#define HD    256
#define QD    (NH*HD)    // 2048
#define KD    (NKV*HD)   // 1024
#define SCALING 0.0625f  // 256^-0.5
#define SEQ   1024       // per-sequence length (cu_seqlens fixed)

// Scratch (allocation-free rule: __device__ globals)
__device__ float g_Q[L * QD];   // post-proj / post-rope Q  [t][h*HD+d]
__device__ float g_K[L * KD];
__device__ float g_V[L * KD];
__device__ float g_A[L * QD];   // attention output [t][h*HD+d]

// ---------------------------------------------------------------------------
// SGEMM: C[M,N] = A[M,K] @ B[K,N], fp32, all dims multiples of tile sizes.
// 128x128 tile, BK=8, 256 threads, 8x8 per-thread microtile.
// ---------------------------------------------------------------------------
__global__ __launch_bounds__(256)
void sgemm128(const float* __restrict__ A, const float* __restrict__ B,
              float* __restrict__ C, int M, int N, int K)
{
    __shared__ float As[8][128];
    __shared__ float Bs[8][128];

    const int tid = threadIdx.x;
    const int br = blockIdx.y * 128;
    const int bc = blockIdx.x * 128;

    const int ty = tid >> 4;        // 0..15
    const int tx = tid & 15;        // 0..15
    const int m0 = ty * 8;
    const int n0 = tx * 8;

    const int arow = tid >> 1;          // 0..127
    const int acol = (tid & 1) * 4;     // 0 or 4
    const int brow = tid >> 5;          // 0..7
    const int bcol = (tid & 31) * 4;    // 0..124

    const float* Aptr = A + (size_t)(br + arow) * K + acol;
    const float* Bptr = B + (size_t)brow * N + bc + bcol;

    float acc[8][8];
#pragma unroll
    for (int i = 0; i < 8; i++)
#pragma unroll
        for (int j = 0; j < 8; j++) acc[i][j] = 0.f;

    for (int k0 = 0; k0 < K; k0 += 8) {
        float4 a = *(const float4*)(Aptr + k0);
        float4 b = *(const float4*)(Bptr + (size_t)k0 * N);
        As[acol + 0][arow] = a.x;
        As[acol + 1][arow] = a.y;
        As[acol + 2][arow] = a.z;
        As[acol + 3][arow] = a.w;
        *(float4*)&Bs[brow][bcol] = b;
        __syncthreads();

#pragma unroll
        for (int k = 0; k < 8; k++) {
            float ar[8], brr[8];
            *(float4*)(ar)     = *(const float4*)&As[k][m0];
            *(float4*)(ar + 4) = *(const float4*)&As[k][m0 + 4];
            *(float4*)(brr)     = *(const float4*)&Bs[k][n0];
            *(float4*)(brr + 4) = *(const float4*)&Bs[k][n0 + 4];
#pragma unroll
            for (int i = 0; i < 8; i++)
#pragma unroll
                for (int j = 0; j < 8; j++)
                    acc[i][j] += ar[i] * brr[j];
        }
        __syncthreads();
    }

#pragma unroll
    for (int i = 0; i < 8; i++) {
#pragma unroll
        for (int j = 0; j < 8; j += 4) {
            float4 v = make_float4(acc[i][j], acc[i][j+1], acc[i][j+2], acc[i][j+3]);
            *(float4*)&C[(size_t)(br + m0 + i) * N + bc + n0 + j] = v;
        }
    }
}

// ---------------------------------------------------------------------------
// RMSNorm + RoPE, one block (256 thr) per (token, head)
// X layout: [t][h*HD+d], hstride = QD or KD
// ---------------------------------------------------------------------------
__global__ __launch_bounds__(256)
void norm_rope_kernel(float* __restrict__ X, int hstride,
                      const float* __restrict__ w,
                      const float* __restrict__ cosp,
                      const float* __restrict__ sinp)
{
    const int t = blockIdx.x;
    const int h = blockIdx.y;
    const int d = threadIdx.x;

    float* xp = X + (size_t)t * hstride + h * HD;
    float x = xp[d];

    // sum of squares over 256 dims
    float v = x * x;
#pragma unroll
    for (int o = 16; o; o >>= 1) v += __shfl_xor_sync(0xffffffffu, v, o);

    __shared__ float ws[8];
    __shared__ float buf[HD];
    if ((d & 31) == 0) ws[d >> 5] = v;
    __syncthreads();
    float ss = ws[0] + ws[1] + ws[2] + ws[3] + ws[4] + ws[5] + ws[6] + ws[7];

    float r = rsqrtf(ss * (1.0f / HD) + 1e-6f);
    float xn = x * r * (1.0f + w[d]);
    buf[d] = xn;
    __syncthreads();

    float rot = (d < HD / 2) ? -buf[d + HD / 2] : buf[d - HD / 2];
    float c = cosp[(size_t)t * HD + d];
    float s = sinp[(size_t)t * HD + d];
    xp[d] = xn * c + rot * s;
}

// ---------------------------------------------------------------------------
// Flash attention, causal within each 1024-seq (window not binding).
// Block: 256 threads. Tile: 64 q-rows x 64 k-cols, HD=256.
// grid = (16 q-tiles, 4 seqs, 8 heads)
// ---------------------------------------------------------------------------
#define QKV_STRIDE 260   // padded row stride (floats), multiple of 4
#define PS_STRIDE  68

__global__ __launch_bounds__(256)
void attn_kernel()
{
    extern __shared__ float sm[];
    float* Qs = sm;                       // 64 * 260
    float* Ks = Qs + 64 * QKV_STRIDE;     // 64 * 260
    float* Vs = Ks + 64 * QKV_STRIDE;     // 64 * 260
    float* Ps = Vs + 64 * QKV_STRIDE;     // 64 * 68

    const int qt  = blockIdx.x;   // 0..15
    const int seq = blockIdx.y;   // 0..3
    const int h   = blockIdx.z;   // 0..7
    const int kvh = h >> 1;

    const int tid = threadIdx.x;
    const int ty = tid >> 4;      // 0..15
    const int tx = tid & 15;      // 0..15

    const int t0 = seq * SEQ + qt * 64;

    // load Q tile
#pragma unroll
    for (int i = 0; i < 16; i++) {
        int f4 = tid + i * 256;            // 0..4095 float4 slots
        int row = f4 >> 6, c4 = (f4 & 63) << 2;
        *(float4*)&Qs[row * QKV_STRIDE + c4] =
            *(const float4*)&g_Q[(size_t)(t0 + row) * QD + h * HD + c4];
    }

    float m_i[4], l_i[4], O[4][16];
#pragma unroll
    for (int r = 0; r < 4; r++) {
        m_i[r] = -INFINITY;
        l_i[r] = 0.f;
#pragma unroll
        for (int cc = 0; cc < 16; cc++) O[r][cc] = 0.f;
    }

    for (int kt = 0; kt <= qt; kt++) {
        __syncthreads();   // protect Ks/Vs/Ps from previous iteration readers

        const int k0row = seq * SEQ + kt * 64;
#pragma unroll
        for (int i = 0; i < 16; i++) {
            int f4 = tid + i * 256;
            int row = f4 >> 6, c4 = (f4 & 63) << 2;
            *(float4*)&Ks[row * QKV_STRIDE + c4] =
                *(const float4*)&g_K[(size_t)(k0row + row) * KD + kvh * HD + c4];
            *(float4*)&Vs[row * QKV_STRIDE + c4] =
                *(const float4*)&g_V[(size_t)(k0row + row) * KD + kvh * HD + c4];
        }
        __syncthreads();

        // S tile: rows ty*4+r, cols tx + c*16
        float s[4][4];
#pragma unroll
        for (int r = 0; r < 4; r++)
#pragma unroll
            for (int c = 0; c < 4; c++) s[r][c] = 0.f;

        for (int d = 0; d < HD; d += 4) {
            float4 qv[4], kv[4];
#pragma unroll
            for (int r = 0; r < 4; r++)
                qv[r] = *(const float4*)&Qs[(ty * 4 + r) * QKV_STRIDE + d];
#pragma unroll
            for (int c = 0; c < 4; c++)
                kv[c] = *(const float4*)&Ks[(tx + c * 16) * QKV_STRIDE + d];
#pragma unroll
            for (int r = 0; r < 4; r++)
#pragma unroll
                for (int c = 0; c < 4; c++) {
                    s[r][c] += qv[r].x * kv[c].x + qv[r].y * kv[c].y
                             + qv[r].z * kv[c].z + qv[r].w * kv[c].w;
                }
        }

        // scale + causal mask on diagonal tile
#pragma unroll
        for (int r = 0; r < 4; r++)
#pragma unroll
            for (int c = 0; c < 4; c++) {
                s[r][c] *= SCALING;
                if (kt == qt && (tx + c * 16) > (ty * 4 + r)) s[r][c] = -INFINITY;
            }

        // online softmax update
#pragma unroll
        for (int r = 0; r < 4; r++) {
            float rm = s[r][0];
#pragma unroll
            for (int c = 1; c < 4; c++) rm = fmaxf(rm, s[r][c]);
#pragma unroll
            for (int o = 8; o; o >>= 1)
                rm = fmaxf(rm, __shfl_xor_sync(0xffffffffu, rm, o, 16));

            float mn = fmaxf(m_i[r], rm);
            float alpha = __expf(m_i[r] - mn);
            float rs = 0.f;
#pragma unroll
            for (int c = 0; c < 4; c++) {
                float p = __expf(s[r][c] - mn);
                Ps[(ty * 4 + r) * PS_STRIDE + tx + c * 16] = p;
                rs += p;
            }
#pragma unroll
            for (int o = 8; o; o >>= 1)
                rs += __shfl_xor_sync(0xffffffffu, rs, o, 16);

            l_i[r] = l_i[r] * alpha + rs;
            m_i[r] = mn;
#pragma unroll
            for (int cc = 0; cc < 16; cc++) O[r][cc] *= alpha;
        }
        __syncthreads();

        // O += P @ V
        for (int j = 0; j < 64; j++) {
            float pj[4];
#pragma unroll
            for (int r = 0; r < 4; r++) pj[r] = Ps[(ty * 4 + r) * PS_STRIDE + j];
#pragma unroll
            for (int cc = 0; cc < 16; cc++) {
                float vv = Vs[j * QKV_STRIDE + tx + cc * 16];
#pragma unroll
                for (int r = 0; r < 4; r++) O[r][cc] += pj[r] * vv;
            }
        }
    }

    // epilogue
#pragma unroll
    for (int r = 0; r < 4; r++) {
        float inv = 1.0f / l_i[r];
#pragma unroll
        for (int cc = 0; cc < 16; cc++) {
            g_A[(size_t)(t0 + ty * 4 + r) * QD + h * HD + tx + cc * 16] = O[r][cc] * inv;
        }
    }
}

// ---------------------------------------------------------------------------
// launch
// ---------------------------------------------------------------------------
extern "C" void kernel_launch(void* const* d_in, const int* in_sizes, int n_in,
                              void* d_out, int out_size)
{
    (void)in_sizes; (void)n_in; (void)out_size;
    const float* hs   = (const float*)d_in[0];
    const float* cosp = (const float*)d_in[1];
    const float* sinp = (const float*)d_in[2];
    const float* Wq   = (const float*)d_in[3];
    const float* Wk   = (const float*)d_in[4];
    const float* Wv   = (const float*)d_in[5];
    const float* Wo   = (const float*)d_in[6];
    const float* qw   = (const float*)d_in[7];
    const float* kw   = (const float*)d_in[8];
    float* out = (float*)d_out;

    float *pQ, *pK, *pV, *pA;
    cudaGetSymbolAddress((void**)&pQ, g_Q);
    cudaGetSymbolAddress((void**)&pK, g_K);
    cudaGetSymbolAddress((void**)&pV, g_V);
    cudaGetSymbolAddress((void**)&pA, g_A);

    // 1. QKV projections
    sgemm128<<<dim3(QD / 128, L / 128), 256>>>(hs, Wq, pQ, L, QD, HID);
    sgemm128<<<dim3(KD / 128, L / 128), 256>>>(hs, Wk, pK, L, KD, HID);
    sgemm128<<<dim3(KD / 128, L / 128), 256>>>(hs, Wv, pV, L, KD, HID);

    // 2. RMSNorm + RoPE
    norm_rope_kernel<<<dim3(L, NH), 256>>>(pQ, QD, qw, cosp, sinp);
    norm_rope_kernel<<<dim3(L, NKV), 256>>>(pK, KD, kw, cosp, sinp);

    // 3. attention
    const int smem = (3 * 64 * QKV_STRIDE + 64 * PS_STRIDE) * (int)sizeof(float);
    cudaFuncSetAttribute(attn_kernel, cudaFuncAttributeMaxDynamicSharedMemorySize, smem);
    attn_kernel<<<dim3(SEQ / 64 /*16*/, L / SEQ /*4*/, NH), 256, smem>>>();

    // 4. output projection
    sgemm128<<<dim3(HID / 128, L / 128), 256>>>(pA, Wo, out, L, HID, QD);
}

// round 2
// speedup vs baseline: 2.2352x; 2.2352x over previous
#include <cuda_runtime.h>
#include <cuda_bf16.h>
#include <math.h>
#include <stdint.h>

// ---------------------------------------------------------------------------
// Problem constants
// ---------------------------------------------------------------------------
#define L     4096
#define HID   2560
#define NH    8
#define NKV   4
#define HD    256
#define QD    (NH*HD)    // 2048
#define KD    (NKV*HD)   // 1024
#define SCALING 0.0625f
#define SEQ   1024

// Scratch
__device__ float g_Q[L * QD];
__device__ float g_K[L * KD];
__device__ float g_V[L * KD];
__device__ float g_A[L * QD];
__device__ float g_HSr[L * HID];     // tf32-rounded hidden states
__device__ float g_Wqr[HID * QD];
__device__ float g_Wkr[HID * KD];
__device__ float g_Wvr[HID * KD];
__device__ float g_Wor[QD * HID];

// ---------------------------------------------------------------------------
// tf32 rounding pre-pass (RNA) — keeps mma numerics clean
// ---------------------------------------------------------------------------
__global__ void round_tf32_kernel(const float* __restrict__ in,
                                  float* __restrict__ out, int n4)
{
    int i = blockIdx.x * blockDim.x + threadIdx.x;
    if (i >= n4) return;
    float4 v = ((const float4*)in)[i];
    uint32_t a, b, c, d;
    asm("cvt.rna.tf32.f32 %0, %1;" : "=r"(a) : "f"(v.x));
    asm("cvt.rna.tf32.f32 %0, %1;" : "=r"(b) : "f"(v.y));
    asm("cvt.rna.tf32.f32 %0, %1;" : "=r"(c) : "f"(v.z));
    asm("cvt.rna.tf32.f32 %0, %1;" : "=r"(d) : "f"(v.w));
    ((uint4*)out)[i] = make_uint4(a, b, c, d);
}

// ---------------------------------------------------------------------------
// TF32 tensor-core GEMM: C[M,N] = A[M,K] @ B[K,N]
// 128x128x32 block tile, 256 threads, 8 warps (2x4), warp tile 64x32.
// mma.sync.m16n8k8.tf32, cp.async double-buffered smem.
// ---------------------------------------------------------------------------
#define SA 36            // A smem row stride (floats), conflict-free frag loads
#define SB 132           // B smem row stride (floats)
#define ABUF (128*SA)    // 4608 floats per stage
#define BBUF (32*SB)     // 4224 floats per stage
#define GEMM_SMEM ((2*ABUF + 2*BBUF) * 4)   // 70656 bytes

__device__ __forceinline__ void cpasync16(uint32_t s, const void* g) {
    asm volatile("cp.async.cg.shared.global [%0], [%1], 16;" :: "r"(s), "l"(g));
}

__global__ __launch_bounds__(256)
void tf32gemm(const float* __restrict__ A, const float* __restrict__ B,
              float* __restrict__ C, int M, int N, int K)
{
    extern __shared__ float sh[];
    float* As = sh;                 // [2][ABUF]
    float* Bs = sh + 2 * ABUF;      // [2][BBUF]

    const int tid  = threadIdx.x;
    const int lane = tid & 31, wid = tid >> 5;
    const int wm = wid >> 2, wn = wid & 3;     // 2 x 4 warp grid
    const int g = lane >> 2, t = lane & 3;
    const int br = blockIdx.y * 128, bc = blockIdx.x * 128;

    const uint32_t sbase = (uint32_t)__cvta_generic_to_shared(sh);

    float acc[4][4][4];
#pragma unroll
    for (int mt = 0; mt < 4; mt++)
#pragma unroll
        for (int nt = 0; nt < 4; nt++)
#pragma unroll
            for (int r = 0; r < 4; r++) acc[mt][nt][r] = 0.f;

    auto issue_copy = [&](int kb, int buf) {
        const float* Ag = A + (size_t)br * K + kb * 32;
        const float* Bg = B + (size_t)(kb * 32) * N + bc;
#pragma unroll
        for (int i = 0; i < 4; i++) {
            int f = tid + i * 256;
            int ar = f >> 3, ak = (f & 7) * 4;
            cpasync16(sbase + (uint32_t)(buf * ABUF + ar * SA + ak) * 4,
                      Ag + (size_t)ar * K + ak);
            int bk = f >> 5, bc4 = (f & 31) * 4;
            cpasync16(sbase + (uint32_t)(2 * ABUF + buf * BBUF + bk * SB + bc4) * 4,
                      Bg + (size_t)bk * N + bc4);
        }
        asm volatile("cp.async.commit_group;" ::: "memory");
    };

    const int nkb = K >> 5;
    issue_copy(0, 0);

    for (int kb = 0; kb < nkb; kb++) {
        const int cur = kb & 1;
        if (kb + 1 < nkb) {
            issue_copy(kb + 1, cur ^ 1);
            asm volatile("cp.async.wait_group 1;" ::: "memory");
        } else {
            asm volatile("cp.async.wait_group 0;" ::: "memory");
        }
        __syncthreads();

        const float* Ab = As + cur * ABUF;
        const float* Bb = Bs + cur * BBUF;

#pragma unroll
        for (int ks = 0; ks < 4; ks++) {
            const int kbase = ks * 8;
            uint32_t af[4][4], bf[4][2];
#pragma unroll
            for (int mt = 0; mt < 4; mt++) {
                const float* p = Ab + (wm * 64 + mt * 16) * SA + kbase;
                af[mt][0] = __float_as_uint(p[g * SA + t]);
                af[mt][1] = __float_as_uint(p[(g + 8) * SA + t]);
                af[mt][2] = __float_as_uint(p[g * SA + t + 4]);
                af[mt][3] = __float_as_uint(p[(g + 8) * SA + t + 4]);
            }
#pragma unroll
            for (int nt = 0; nt < 4; nt++) {
                const float* p = Bb + kbase * SB + wn * 32 + nt * 8 + g;
                bf[nt][0] = __float_as_uint(p[t * SB]);
                bf[nt][1] = __float_as_uint(p[(t + 4) * SB]);
            }
#pragma unroll
            for (int mt = 0; mt < 4; mt++)
#pragma unroll
                for (int nt = 0; nt < 4; nt++)
                    asm volatile(
                        "mma.sync.aligned.m16n8k8.row.col.f32.tf32.tf32.f32 "
                        "{%0,%1,%2,%3}, {%4,%5,%6,%7}, {%8,%9}, {%0,%1,%2,%3};"
                        : "+f"(acc[mt][nt][0]), "+f"(acc[mt][nt][1]),
                          "+f"(acc[mt][nt][2]), "+f"(acc[mt][nt][3])
                        : "r"(af[mt][0]), "r"(af[mt][1]),
                          "r"(af[mt][2]), "r"(af[mt][3]),
                          "r"(bf[nt][0]), "r"(bf[nt][1]));
        }
        __syncthreads();
    }

    // epilogue
#pragma unroll
    for (int mt = 0; mt < 4; mt++) {
        const int r0 = br + wm * 64 + mt * 16 + g;
#pragma unroll
        for (int nt = 0; nt < 4; nt++) {
            const int c0 = bc + wn * 32 + nt * 8 + t * 2;
            *(float2*)&C[(size_t)r0 * N + c0] =
                make_float2(acc[mt][nt][0], acc[mt][nt][1]);
            *(float2*)&C[(size_t)(r0 + 8) * N + c0] =
                make_float2(acc[mt][nt][2], acc[mt][nt][3]);
        }
    }
}

// ---------------------------------------------------------------------------
// RMSNorm + RoPE (unchanged)
// ---------------------------------------------------------------------------
__global__ __launch_bounds__(256)
void norm_rope_kernel(float* __restrict__ X, int hstride,
                      const float* __restrict__ w,
                      const float* __restrict__ cosp,
                      const float* __restrict__ sinp)
{
    const int t = blockIdx.x;
    const int h = blockIdx.y;
    const int d = threadIdx.x;

    float* xp = X + (size_t)t * hstride + h * HD;
    float x = xp[d];

    float v = x * x;
#pragma unroll
    for (int o = 16; o; o >>= 1) v += __shfl_xor_sync(0xffffffffu, v, o);

    __shared__ float ws[8];
    __shared__ float buf[HD];
    if ((d & 31) == 0) ws[d >> 5] = v;
    __syncthreads();
    float ss = ws[0] + ws[1] + ws[2] + ws[3] + ws[4] + ws[5] + ws[6] + ws[7];

    float r = rsqrtf(ss * (1.0f / HD) + 1e-6f);
    float xn = x * r * (1.0f + w[d]);
    buf[d] = xn;
    __syncthreads();

    float rot = (d < HD / 2) ? -buf[d + HD / 2] : buf[d - HD / 2];
    float c = cosp[(size_t)t * HD + d];
    float s = sinp[(size_t)t * HD + d];
    xp[d] = xn * c + rot * s;
}

// ---------------------------------------------------------------------------
// Flash attention (fp32, unchanged except tf32-rounded output for out-proj)
// ---------------------------------------------------------------------------
#define QKV_STRIDE 260
#define PS_STRIDE  68

__global__ __launch_bounds__(256)
void attn_kernel()
{
    extern __shared__ float sm[];
    float* Qs = sm;
    float* Ks = Qs + 64 * QKV_STRIDE;
    float* Vs = Ks + 64 * QKV_STRIDE;
    float* Ps = Vs + 64 * QKV_STRIDE;

    const int qt  = blockIdx.x;
    const int seq = blockIdx.y;
    const int h   = blockIdx.z;
    const int kvh = h >> 1;

    const int tid = threadIdx.x;
    const int ty = tid >> 4;
    const int tx = tid & 15;

    const int t0 = seq * SEQ + qt * 64;

#pragma unroll
    for (int i = 0; i < 16; i++) {
        int f4 = tid + i * 256;
        int row = f4 >> 6, c4 = (f4 & 63) << 2;
        *(float4*)&Qs[row * QKV_STRIDE + c4] =
            *(const float4*)&g_Q[(size_t)(t0 + row) * QD + h * HD + c4];
    }

    float m_i[4], l_i[4], O[4][16];
#pragma unroll
    for (int r = 0; r < 4; r++) {
        m_i[r] = -INFINITY;
        l_i[r] = 0.f;
#pragma unroll
        for (int cc = 0; cc < 16; cc++) O[r][cc] = 0.f;
    }

    for (int kt = 0; kt <= qt; kt++) {
        __syncthreads();

        const int k0row = seq * SEQ + kt * 64;
#pragma unroll
        for (int i = 0; i < 16; i++) {
            int f4 = tid + i * 256;
            int row = f4 >> 6, c4 = (f4 & 63) << 2;
            *(float4*)&Ks[row * QKV_STRIDE + c4] =
                *(const float4*)&g_K[(size_t)(k0row + row) * KD + kvh * HD + c4];
            *(float4*)&Vs[row * QKV_STRIDE + c4] =
                *(const float4*)&g_V[(size_t)(k0row + row) * KD + kvh * HD + c4];
        }
        __syncthreads();

        float s[4][4];
#pragma unroll
        for (int r = 0; r < 4; r++)
#pragma unroll
            for (int c = 0; c < 4; c++) s[r][c] = 0.f;

        for (int d = 0; d < HD; d += 4) {
            float4 qv[4], kv[4];
#pragma unroll
            for (int r = 0; r < 4; r++)
                qv[r] = *(const float4*)&Qs[(ty * 4 + r) * QKV_STRIDE + d];
#pragma unroll
            for (int c = 0; c < 4; c++)
                kv[c] = *(const float4*)&Ks[(tx + c * 16) * QKV_STRIDE + d];
#pragma unroll
            for (int r = 0; r < 4; r++)
#pragma unroll
                for (int c = 0; c < 4; c++)
                    s[r][c] += qv[r].x * kv[c].x + qv[r].y * kv[c].y
                             + qv[r].z * kv[c].z + qv[r].w * kv[c].w;
        }

#pragma unroll
        for (int r = 0; r < 4; r++)
#pragma unroll
            for (int c = 0; c < 4; c++) {
                s[r][c] *= SCALING;
                if (kt == qt && (tx + c * 16) > (ty * 4 + r)) s[r][c] = -INFINITY;
            }

#pragma unroll
        for (int r = 0; r < 4; r++) {
            float rm = s[r][0];
#pragma unroll
            for (int c = 1; c < 4; c++) rm = fmaxf(rm, s[r][c]);
#pragma unroll
            for (int o = 8; o; o >>= 1)
                rm = fmaxf(rm, __shfl_xor_sync(0xffffffffu, rm, o, 16));

            float mn = fmaxf(m_i[r], rm);
            float alpha = __expf(m_i[r] - mn);
            float rs = 0.f;
#pragma unroll
            for (int c = 0; c < 4; c++) {
                float p = __expf(s[r][c] - mn);
                Ps[(ty * 4 + r) * PS_STRIDE + tx + c * 16] = p;
                rs += p;
            }
#pragma unroll
            for (int o = 8; o; o >>= 1)
                rs += __shfl_xor_sync(0xffffffffu, rs, o, 16);

            l_i[r] = l_i[r] * alpha + rs;
            m_i[r] = mn;
#pragma unroll
            for (int cc = 0; cc < 16; cc++) O[r][cc] *= alpha;
        }
        __syncthreads();

        for (int j = 0; j < 64; j++) {
            float pj[4];
#pragma unroll
            for (int r = 0; r < 4; r++) pj[r] = Ps[(ty * 4 + r) * PS_STRIDE + j];
#pragma unroll
            for (int cc = 0; cc < 16; cc++) {
                float vv = Vs[j * QKV_STRIDE + tx + cc * 16];
#pragma unroll
                for (int r = 0; r < 4; r++) O[r][cc] += pj[r] * vv;
            }
        }
    }

#pragma unroll
    for (int r = 0; r < 4; r++) {
        float inv = 1.0f / l_i[r];
#pragma unroll
        for (int cc = 0; cc < 16; cc++) {
            float o = O[r][cc] * inv;
            uint32_t u;
            asm("cvt.rna.tf32.f32 %0, %1;" : "=r"(u) : "f"(o));
            g_A[(size_t)(t0 + ty * 4 + r) * QD + h * HD + tx + cc * 16] =
                __uint_as_float(u);
        }
    }
}

// ---------------------------------------------------------------------------
// launch
// ---------------------------------------------------------------------------
extern "C" void kernel_launch(void* const* d_in, const int* in_sizes, int n_in,
                              void* d_out, int out_size)
{
    (void)in_sizes; (void)n_in; (void)out_size;
    const float* hs   = (const float*)d_in[0];
    const float* cosp = (const float*)d_in[1];
    const float* sinp = (const float*)d_in[2];
    const float* Wq   = (const float*)d_in[3];
    const float* Wk   = (const float*)d_in[4];
    const float* Wv   = (const float*)d_in[5];
    const float* Wo   = (const float*)d_in[6];
    const float* qw   = (const float*)d_in[7];
    const float* kw   = (const float*)d_in[8];
    float* out = (float*)d_out;

    float *pQ, *pK, *pV, *pA, *pHS, *pWq, *pWk, *pWv, *pWo;
    cudaGetSymbolAddress((void**)&pQ,  g_Q);
    cudaGetSymbolAddress((void**)&pK,  g_K);
    cudaGetSymbolAddress((void**)&pV,  g_V);
    cudaGetSymbolAddress((void**)&pA,  g_A);
    cudaGetSymbolAddress((void**)&pHS, g_HSr);
    cudaGetSymbolAddress((void**)&pWq, g_Wqr);
    cudaGetSymbolAddress((void**)&pWk, g_Wkr);
    cudaGetSymbolAddress((void**)&pWv, g_Wvr);
    cudaGetSymbolAddress((void**)&pWo, g_Wor);

    // 0. tf32-round inputs & weights
    {
        int n;
        n = L * HID / 4;  round_tf32_kernel<<<(n + 255) / 256, 256>>>(hs, pHS, n);
        n = HID * QD / 4; round_tf32_kernel<<<(n + 255) / 256, 256>>>(Wq, pWq, n);
        n = HID * KD / 4; round_tf32_kernel<<<(n + 255) / 256, 256>>>(Wk, pWk, n);
        n = HID * KD / 4; round_tf32_kernel<<<(n + 255) / 256, 256>>>(Wv, pWv, n);
        n = QD * HID / 4; round_tf32_kernel<<<(n + 255) / 256, 256>>>(Wo, pWo, n);
    }

    cudaFuncSetAttribute(tf32gemm, cudaFuncAttributeMaxDynamicSharedMemorySize,
                         GEMM_SMEM);

    // 1. QKV projections (tensor cores, tf32)
    tf32gemm<<<dim3(QD / 128, L / 128), 256, GEMM_SMEM>>>(pHS, pWq, pQ, L, QD, HID);
    tf32gemm<<<dim3(KD / 128, L / 128), 256, GEMM_SMEM>>>(pHS, pWk, pK, L, KD, HID);
    tf32gemm<<<dim3(KD / 128, L / 128), 256, GEMM_SMEM>>>(pHS, pWv, pV, L, KD, HID);

    // 2. RMSNorm + RoPE
    norm_rope_kernel<<<dim3(L, NH), 256>>>(pQ, QD, qw, cosp, sinp);
    norm_rope_kernel<<<dim3(L, NKV), 256>>>(pK, KD, kw, cosp, sinp);

    // 3. attention (fp32)
    const int smem = (3 * 64 * QKV_STRIDE + 64 * PS_STRIDE) * (int)sizeof(float);
    cudaFuncSetAttribute(attn_kernel, cudaFuncAttributeMaxDynamicSharedMemorySize, smem);
    attn_kernel<<<dim3(SEQ / 64, L / SEQ, NH), 256, smem>>>();

    // 4. output projection (tensor cores, tf32)
    tf32gemm<<<dim3(HID / 128, L / 128), 256, GEMM_SMEM>>>(pA, pWo, out, L, HID, QD);
}

// round 3
// speedup vs baseline: 2.3201x; 1.0380x over previous
#include <cuda_runtime.h>
#include <cuda_bf16.h>
#include <math.h>
#include <stdint.h>

// ---------------------------------------------------------------------------
// Problem constants
// ---------------------------------------------------------------------------
#define L     4096
#define HID   2560
#define NH    8
#define NKV   4
#define HD    256
#define QD    (NH*HD)    // 2048
#define KD    (NKV*HD)   // 1024
#define SCALING 0.0625f
#define SEQ   1024

// Scratch
__device__ float g_Q[L * QD];        // raw Q projection
__device__ float g_K[L * KD];
__device__ float g_V[L * KD];
__device__ float g_A[L * QD];        // attention out (tf32-rounded)
__device__ float g_HSr[L * HID];
__device__ float g_Wqr[HID * QD];
__device__ float g_Wkr[HID * KD];
__device__ float g_Wvr[HID * KD];
__device__ float g_Wor[QD * HID];
// hi/lo tf32 splits for attention
__device__ float g_Qh[L * QD];
__device__ float g_Ql[L * QD];
__device__ float g_Kh[L * KD];
__device__ float g_Kl[L * KD];
__device__ float g_Vh[L * KD];
__device__ float g_Vl[L * KD];

// ---------------------------------------------------------------------------
// helpers
// ---------------------------------------------------------------------------
__device__ __forceinline__ uint32_t tf32r(float x) {
    uint32_t u;
    asm("cvt.rna.tf32.f32 %0, %1;" : "=r"(u) : "f"(x));
    return u;
}
__device__ __forceinline__ void split_tf32(float x, float& hi, float& lo) {
    uint32_t h = tf32r(x);
    hi = __uint_as_float(h);
    lo = __uint_as_float(tf32r(x - hi));
}
__device__ __forceinline__ void mma8(float* c, const uint32_t* a, const uint32_t* b) {
    asm volatile(
        "mma.sync.aligned.m16n8k8.row.col.f32.tf32.tf32.f32 "
        "{%0,%1,%2,%3}, {%4,%5,%6,%7}, {%8,%9}, {%0,%1,%2,%3};"
        : "+f"(c[0]), "+f"(c[1]), "+f"(c[2]), "+f"(c[3])
        : "r"(a[0]), "r"(a[1]), "r"(a[2]), "r"(a[3]), "r"(b[0]), "r"(b[1]));
}
__device__ __forceinline__ void cpasync16(uint32_t s, const void* g) {
    asm volatile("cp.async.cg.shared.global [%0], [%1], 16;" :: "r"(s), "l"(g));
}

// ---------------------------------------------------------------------------
// tf32 rounding pre-pass
// ---------------------------------------------------------------------------
__global__ void round_tf32_kernel(const float* __restrict__ in,
                                  float* __restrict__ out, int n4)
{
    int i = blockIdx.x * blockDim.x + threadIdx.x;
    if (i >= n4) return;
    float4 v = ((const float4*)in)[i];
    ((uint4*)out)[i] = make_uint4(tf32r(v.x), tf32r(v.y), tf32r(v.z), tf32r(v.w));
}

// hi/lo split pre-pass (for V)
__global__ void split_tf32_kernel(const float* __restrict__ in,
                                  float* __restrict__ oh,
                                  float* __restrict__ ol, int n4)
{
    int i = blockIdx.x * blockDim.x + threadIdx.x;
    if (i >= n4) return;
    float4 v = ((const float4*)in)[i];
    float4 h, l;
    split_tf32(v.x, h.x, l.x);
    split_tf32(v.y, h.y, l.y);
    split_tf32(v.z, h.z, l.z);
    split_tf32(v.w, h.w, l.w);
    ((float4*)oh)[i] = h;
    ((float4*)ol)[i] = l;
}

// ---------------------------------------------------------------------------
// TF32 GEMM (unchanged from round 2)
// ---------------------------------------------------------------------------
#define SA 36
#define SB 132
#define ABUF (128*SA)
#define BBUF (32*SB)
#define GEMM_SMEM ((2*ABUF + 2*BBUF) * 4)

__global__ __launch_bounds__(256)
void tf32gemm(const float* __restrict__ A, const float* __restrict__ B,
              float* __restrict__ C, int M, int N, int K)
{
    extern __shared__ float sh[];
    float* As = sh;
    float* Bs = sh + 2 * ABUF;

    const int tid  = threadIdx.x;
    const int lane = tid & 31, wid = tid >> 5;
    const int wm = wid >> 2, wn = wid & 3;
    const int g = lane >> 2, t = lane & 3;
    const int br = blockIdx.y * 128, bc = blockIdx.x * 128;

    const uint32_t sbase = (uint32_t)__cvta_generic_to_shared(sh);

    float acc[4][4][4];
#pragma unroll
    for (int mt = 0; mt < 4; mt++)
#pragma unroll
        for (int nt = 0; nt < 4; nt++)
#pragma unroll
            for (int r = 0; r < 4; r++) acc[mt][nt][r] = 0.f;

    auto issue_copy = [&](int kb, int buf) {
        const float* Ag = A + (size_t)br * K + kb * 32;
        const float* Bg = B + (size_t)(kb * 32) * N + bc;
#pragma unroll
        for (int i = 0; i < 4; i++) {
            int f = tid + i * 256;
            int ar = f >> 3, ak = (f & 7) * 4;
            cpasync16(sbase + (uint32_t)(buf * ABUF + ar * SA + ak) * 4,
                      Ag + (size_t)ar * K + ak);
            int bk = f >> 5, bc4 = (f & 31) * 4;
            cpasync16(sbase + (uint32_t)(2 * ABUF + buf * BBUF + bk * SB + bc4) * 4,
                      Bg + (size_t)bk * N + bc4);
        }
        asm volatile("cp.async.commit_group;" ::: "memory");
    };

    const int nkb = K >> 5;
    issue_copy(0, 0);

    for (int kb = 0; kb < nkb; kb++) {
        const int cur = kb & 1;
        if (kb + 1 < nkb) {
            issue_copy(kb + 1, cur ^ 1);
            asm volatile("cp.async.wait_group 1;" ::: "memory");
        } else {
            asm volatile("cp.async.wait_group 0;" ::: "memory");
        }
        __syncthreads();

        const float* Ab = As + cur * ABUF;
        const float* Bb = Bs + cur * BBUF;

#pragma unroll
        for (int ks = 0; ks < 4; ks++) {
            const int kbase = ks * 8;
            uint32_t af[4][4], bf[4][2];
#pragma unroll
            for (int mt = 0; mt < 4; mt++) {
                const float* p = Ab + (wm * 64 + mt * 16) * SA + kbase;
                af[mt][0] = __float_as_uint(p[g * SA + t]);
                af[mt][1] = __float_as_uint(p[(g + 8) * SA + t]);
                af[mt][2] = __float_as_uint(p[g * SA + t + 4]);
                af[mt][3] = __float_as_uint(p[(g + 8) * SA + t + 4]);
            }
#pragma unroll
            for (int nt = 0; nt < 4; nt++) {
                const float* p = Bb + kbase * SB + wn * 32 + nt * 8 + g;
                bf[nt][0] = __float_as_uint(p[t * SB]);
                bf[nt][1] = __float_as_uint(p[(t + 4) * SB]);
            }
#pragma unroll
            for (int mt = 0; mt < 4; mt++)
#pragma unroll
                for (int nt = 0; nt < 4; nt++)
                    mma8(acc[mt][nt], af[mt], bf[nt]);
        }
        __syncthreads();
    }

#pragma unroll
    for (int mt = 0; mt < 4; mt++) {
        const int r0 = br + wm * 64 + mt * 16 + g;
#pragma unroll
        for (int nt = 0; nt < 4; nt++) {
            const int c0 = bc + wn * 32 + nt * 8 + t * 2;
            *(float2*)&C[(size_t)r0 * N + c0] =
                make_float2(acc[mt][nt][0], acc[mt][nt][1]);
            *(float2*)&C[(size_t)(r0 + 8) * N + c0] =
                make_float2(acc[mt][nt][2], acc[mt][nt][3]);
        }
    }
}

// ---------------------------------------------------------------------------
// RMSNorm + RoPE, now writes tf32 hi/lo split
// ---------------------------------------------------------------------------
__global__ __launch_bounds__(256)
void norm_rope_split_kernel(const float* __restrict__ X, int hstride,
                            const float* __restrict__ w,
                            const float* __restrict__ cosp,
                            const float* __restrict__ sinp,
                            float* __restrict__ Xh, float* __restrict__ Xl)
{
    const int t = blockIdx.x;
    const int h = blockIdx.y;
    const int d = threadIdx.x;

    const size_t off = (size_t)t * hstride + h * HD + d;
    float x = X[off];

    float v = x * x;
#pragma unroll
    for (int o = 16; o; o >>= 1) v += __shfl_xor_sync(0xffffffffu, v, o);

    __shared__ float ws[8];
    __shared__ float buf[HD];
    if ((d & 31) == 0) ws[d >> 5] = v;
    __syncthreads();
    float ss = ws[0] + ws[1] + ws[2] + ws[3] + ws[4] + ws[5] + ws[6] + ws[7];

    float r = rsqrtf(ss * (1.0f / HD) + 1e-6f);
    float xn = x * r * (1.0f + w[d]);
    buf[d] = xn;
    __syncthreads();

    float rot = (d < HD / 2) ? -buf[d + HD / 2] : buf[d - HD / 2];
    float c = cosp[(size_t)t * HD + d];
    float s = sinp[(size_t)t * HD + d];
    float xr = xn * c + rot * s;

    float hi, lo;
    split_tf32(xr, hi, lo);
    Xh[off] = hi;
    Xl[off] = lo;
}

// ---------------------------------------------------------------------------
// Flash attention on tensor cores (3xTF32 for S and PV)
// Block: 256 thr (8 warps). Tile 64 q-rows x 64 k-cols, d-chunks of 64.
// ---------------------------------------------------------------------------
#define SQ 260           // resident Q smem stride
#define SC 68            // chunk / P smem stride
// smem offsets (floats)
#define OQH 0
#define OQL (OQH + 64*SQ)
#define OKH (OQL + 64*SQ)
#define OKL (OKH + 64*SC)
#define OPH (OKL + 64*SC)
#define OPL (OPH + 64*SC)
#define OPM (OPL + 64*SC)
#define OPS (OPM + 128)
#define ATT_SMEM ((OPS + 128) * 4)

__global__ __launch_bounds__(256, 1)
void attn_mma_kernel()
{
    extern __shared__ float sm[];
    float* Qh = sm + OQH;
    float* Ql = sm + OQL;
    float* Kh = sm + OKH;   // reused for V chunks
    float* Kl = sm + OKL;
    float* Ph = sm + OPH;
    float* Pl = sm + OPL;
    float* pm = sm + OPM;   // [2][64] row-max partials
    float* ps = sm + OPS;   // [2][64] row-sum partials

    const int qt  = blockIdx.x;
    const int seq = blockIdx.y;
    const int h   = blockIdx.z;
    const int kvh = h >> 1;

    const int tid  = threadIdx.x;
    const int lane = tid & 31, wid = tid >> 5;
    const int wm = wid >> 1, wn = wid & 1;    // 4 x 2 warp grid (16 rows x 32 cols)
    const int g = lane >> 2, t = lane & 3;

    const int t0 = seq * SEQ + qt * 64;
    const uint32_t sb = (uint32_t)__cvta_generic_to_shared(sm);

    // resident Q hi/lo load
    {
        const float* gqh = g_Qh + (size_t)t0 * QD + h * HD;
        const float* gql = g_Ql + (size_t)t0 * QD + h * HD;
#pragma unroll
        for (int i = 0; i < 16; i++) {
            int f = tid + i * 256;
            int row = f >> 6, c4 = (f & 63) * 4;
            cpasync16(sb + (uint32_t)(OQH + row * SQ + c4) * 4, gqh + (size_t)row * QD + c4);
            cpasync16(sb + (uint32_t)(OQL + row * SQ + c4) * 4, gql + (size_t)row * QD + c4);
        }
        asm volatile("cp.async.commit_group;" ::: "memory");
        asm volatile("cp.async.wait_group 0;" ::: "memory");
    }
    __syncthreads();

    float O[4][4][4];      // [dchunk][ntile][reg]
#pragma unroll
    for (int dc = 0; dc < 4; dc++)
#pragma unroll
        for (int nt = 0; nt < 4; nt++)
#pragma unroll
            for (int r = 0; r < 4; r++) O[dc][nt][r] = 0.f;
    float m0 = -INFINITY, m1 = -INFINITY, l0 = 0.f, l1 = 0.f;

    for (int kt = 0; kt <= qt; kt++) {
        const int k0 = seq * SEQ + kt * 64;

        float S[4][4];
#pragma unroll
        for (int nt = 0; nt < 4; nt++)
#pragma unroll
            for (int r = 0; r < 4; r++) S[nt][r] = 0.f;

        // ---- S = Q @ K^T over 4 d-chunks ----
        for (int dc = 0; dc < 4; dc++) {
            __syncthreads();   // chunk slot free
#pragma unroll
            for (int i = 0; i < 4; i++) {
                int f = tid + i * 256;
                int row = f >> 4, c4 = (f & 15) * 4;
                size_t src = (size_t)(k0 + row) * KD + kvh * HD + dc * 64 + c4;
                cpasync16(sb + (uint32_t)(OKH + row * SC + c4) * 4, g_Kh + src);
                cpasync16(sb + (uint32_t)(OKL + row * SC + c4) * 4, g_Kl + src);
            }
            asm volatile("cp.async.commit_group;" ::: "memory");
            asm volatile("cp.async.wait_group 0;" ::: "memory");
            __syncthreads();

#pragma unroll
            for (int ks = 0; ks < 8; ks++) {
                uint32_t ah[4], al[4];
                const int ab = (wm * 16 + g) * SQ + dc * 64 + ks * 8 + t;
                ah[0] = __float_as_uint(Qh[ab]);
                ah[1] = __float_as_uint(Qh[ab + 8 * SQ]);
                ah[2] = __float_as_uint(Qh[ab + 4]);
                ah[3] = __float_as_uint(Qh[ab + 8 * SQ + 4]);
                al[0] = __float_as_uint(Ql[ab]);
                al[1] = __float_as_uint(Ql[ab + 8 * SQ]);
                al[2] = __float_as_uint(Ql[ab + 4]);
                al[3] = __float_as_uint(Ql[ab + 8 * SQ + 4]);
#pragma unroll
                for (int nt = 0; nt < 4; nt++) {
                    const int kb = (wn * 32 + nt * 8 + g) * SC + ks * 8 + t;
                    uint32_t bh[2], bl[2];
                    bh[0] = __float_as_uint(Kh[kb]);
                    bh[1] = __float_as_uint(Kh[kb + 4]);
                    bl[0] = __float_as_uint(Kl[kb]);
                    bl[1] = __float_as_uint(Kl[kb + 4]);
                    mma8(S[nt], ah, bh);
                    mma8(S[nt], ah, bl);
                    mma8(S[nt], al, bh);
                }
            }
        }

        // ---- scale + mask ----
#pragma unroll
        for (int nt = 0; nt < 4; nt++) {
#pragma unroll
            for (int r = 0; r < 4; r++) S[nt][r] *= SCALING;
            if (kt == qt) {
                const int cl = wn * 32 + nt * 8 + 2 * t;
                const int rl0 = wm * 16 + g, rl1 = rl0 + 8;
                if (cl     > rl0) S[nt][0] = -INFINITY;
                if (cl + 1 > rl0) S[nt][1] = -INFINITY;
                if (cl     > rl1) S[nt][2] = -INFINITY;
                if (cl + 1 > rl1) S[nt][3] = -INFINITY;
            }
        }

        // ---- online softmax ----
        float rm0 = -INFINITY, rm1 = -INFINITY;
#pragma unroll
        for (int nt = 0; nt < 4; nt++) {
            rm0 = fmaxf(rm0, fmaxf(S[nt][0], S[nt][1]));
            rm1 = fmaxf(rm1, fmaxf(S[nt][2], S[nt][3]));
        }
        rm0 = fmaxf(rm0, __shfl_xor_sync(0xffffffffu, rm0, 1));
        rm0 = fmaxf(rm0, __shfl_xor_sync(0xffffffffu, rm0, 2));
        rm1 = fmaxf(rm1, __shfl_xor_sync(0xffffffffu, rm1, 1));
        rm1 = fmaxf(rm1, __shfl_xor_sync(0xffffffffu, rm1, 2));
        if (t == 0) {
            pm[wn * 64 + wm * 16 + g]     = rm0;
            pm[wn * 64 + wm * 16 + 8 + g] = rm1;
        }
        __syncthreads();
        rm0 = fmaxf(rm0, pm[(wn ^ 1) * 64 + wm * 16 + g]);
        rm1 = fmaxf(rm1, pm[(wn ^ 1) * 64 + wm * 16 + 8 + g]);

        const float mn0 = fmaxf(m0, rm0), mn1 = fmaxf(m1, rm1);
        const float a0 = __expf(m0 - mn0), a1 = __expf(m1 - mn1);

        float s0 = 0.f, s1 = 0.f;
#pragma unroll
        for (int nt = 0; nt < 4; nt++) {
            float p0 = __expf(S[nt][0] - mn0);
            float p1 = __expf(S[nt][1] - mn0);
            float p2 = __expf(S[nt][2] - mn1);
            float p3 = __expf(S[nt][3] - mn1);
            s0 += p0 + p1;
            s1 += p2 + p3;
            float h0, l0_, h1, l1_, h2, l2_, h3, l3_;
            split_tf32(p0, h0, l0_);
            split_tf32(p1, h1, l1_);
            split_tf32(p2, h2, l2_);
            split_tf32(p3, h3, l3_);
            const int col = wn * 32 + nt * 8 + 2 * t;
            const int r0 = wm * 16 + g, r1 = r0 + 8;
            *(float2*)&Ph[r0 * SC + col] = make_float2(h0, h1);
            *(float2*)&Pl[r0 * SC + col] = make_float2(l0_, l1_);
            *(float2*)&Ph[r1 * SC + col] = make_float2(h2, h3);
            *(float2*)&Pl[r1 * SC + col] = make_float2(l2_, l3_);
        }
        s0 += __shfl_xor_sync(0xffffffffu, s0, 1);
        s0 += __shfl_xor_sync(0xffffffffu, s0, 2);
        s1 += __shfl_xor_sync(0xffffffffu, s1, 1);
        s1 += __shfl_xor_sync(0xffffffffu, s1, 2);
        if (t == 0) {
            ps[wn * 64 + wm * 16 + g]     = s0;
            ps[wn * 64 + wm * 16 + 8 + g] = s1;
        }
        __syncthreads();
        l0 = l0 * a0 + ps[wm * 16 + g]     + ps[64 + wm * 16 + g];
        l1 = l1 * a1 + ps[wm * 16 + 8 + g] + ps[64 + wm * 16 + 8 + g];
        m0 = mn0; m1 = mn1;
#pragma unroll
        for (int dc = 0; dc < 4; dc++)
#pragma unroll
            for (int nt = 0; nt < 4; nt++) {
                O[dc][nt][0] *= a0; O[dc][nt][1] *= a0;
                O[dc][nt][2] *= a1; O[dc][nt][3] *= a1;
            }

        // ---- O += P @ V over 4 d-chunks ----
        for (int dc = 0; dc < 4; dc++) {
            __syncthreads();
#pragma unroll
            for (int i = 0; i < 4; i++) {
                int f = tid + i * 256;
                int row = f >> 4, c4 = (f & 15) * 4;
                size_t src = (size_t)(k0 + row) * KD + kvh * HD + dc * 64 + c4;
                cpasync16(sb + (uint32_t)(OKH + row * SC + c4) * 4, g_Vh + src);
                cpasync16(sb + (uint32_t)(OKL + row * SC + c4) * 4, g_Vl + src);
            }
            asm volatile("cp.async.commit_group;" ::: "memory");
            asm volatile("cp.async.wait_group 0;" ::: "memory");
            __syncthreads();

#pragma unroll
            for (int kk = 0; kk < 8; kk++) {
                uint32_t ah[4], al[4];
                const int ab = (wm * 16 + g) * SC + kk * 8 + t;
                ah[0] = __float_as_uint(Ph[ab]);
                ah[1] = __float_as_uint(Ph[ab + 8 * SC]);
                ah[2] = __float_as_uint(Ph[ab + 4]);
                ah[3] = __float_as_uint(Ph[ab + 8 * SC + 4]);
                al[0] = __float_as_uint(Pl[ab]);
                al[1] = __float_as_uint(Pl[ab + 8 * SC]);
                al[2] = __float_as_uint(Pl[ab + 4]);
                al[3] = __float_as_uint(Pl[ab + 8 * SC + 4]);
#pragma unroll
                for (int nt = 0; nt < 4; nt++) {
                    const int vb = (kk * 8 + t) * SC + wn * 32 + nt * 8 + g;
                    uint32_t bh[2], bl[2];
                    bh[0] = __float_as_uint(Kh[vb]);
                    bh[1] = __float_as_uint(Kh[vb + 4 * SC]);
                    bl[0] = __float_as_uint(Kl[vb]);
                    bl[1] = __float_as_uint(Kl[vb + 4 * SC]);
                    mma8(O[dc][nt], ah, bh);
                    mma8(O[dc][nt], ah, bl);
                    mma8(O[dc][nt], al, bh);
                }
            }
        }
    }

    // ---- epilogue ----
    const float i0 = 1.0f / l0, i1 = 1.0f / l1;
#pragma unroll
    for (int dc = 0; dc < 4; dc++)
#pragma unroll
        for (int nt = 0; nt < 4; nt++) {
            const int col = h * HD + dc * 64 + wn * 32 + nt * 8 + 2 * t;
            const size_t r0 = (size_t)(t0 + wm * 16 + g) * QD + col;
            const size_t r1 = (size_t)(t0 + wm * 16 + 8 + g) * QD + col;
            *(float2*)&g_A[r0] = make_float2(
                __uint_as_float(tf32r(O[dc][nt][0] * i0)),
                __uint_as_float(tf32r(O[dc][nt][1] * i0)));
            *(float2*)&g_A[r1] = make_float2(
                __uint_as_float(tf32r(O[dc][nt][2] * i1)),
                __uint_as_float(tf32r(O[dc][nt][3] * i1)));
        }
}

// ---------------------------------------------------------------------------
// launch
// ---------------------------------------------------------------------------
extern "C" void kernel_launch(void* const* d_in, const int* in_sizes, int n_in,
                              void* d_out, int out_size)
{
    (void)in_sizes; (void)n_in; (void)out_size;
    const float* hs   = (const float*)d_in[0];
    const float* cosp = (const float*)d_in[1];
    const float* sinp = (const float*)d_in[2];
    const float* Wq   = (const float*)d_in[3];
    const float* Wk   = (const float*)d_in[4];
    const float* Wv   = (const float*)d_in[5];
    const float* Wo   = (const float*)d_in[6];
    const float* qw   = (const float*)d_in[7];
    const float* kw   = (const float*)d_in[8];
    float* out = (float*)d_out;

    float *pQ, *pK, *pV, *pA, *pHS, *pWq, *pWk, *pWv, *pWo;
    float *pQh, *pQl, *pKh, *pKl, *pVh, *pVl;
    cudaGetSymbolAddress((void**)&pQ,  g_Q);
    cudaGetSymbolAddress((void**)&pK,  g_K);
    cudaGetSymbolAddress((void**)&pV,  g_V);
    cudaGetSymbolAddress((void**)&pA,  g_A);
    cudaGetSymbolAddress((void**)&pHS, g_HSr);
    cudaGetSymbolAddress((void**)&pWq, g_Wqr);
    cudaGetSymbolAddress((void**)&pWk, g_Wkr);
    cudaGetSymbolAddress((void**)&pWv, g_Wvr);
    cudaGetSymbolAddress((void**)&pWo, g_Wor);
    cudaGetSymbolAddress((void**)&pQh, g_Qh);
    cudaGetSymbolAddress((void**)&pQl, g_Ql);
    cudaGetSymbolAddress((void**)&pKh, g_Kh);
    cudaGetSymbolAddress((void**)&pKl, g_Kl);
    cudaGetSymbolAddress((void**)&pVh, g_Vh);
    cudaGetSymbolAddress((void**)&pVl, g_Vl);

    // 0. tf32-round inputs & weights
    {
        int n;
        n = L * HID / 4;  round_tf32_kernel<<<(n + 255) / 256, 256>>>(hs, pHS, n);
        n = HID * QD / 4; round_tf32_kernel<<<(n + 255) / 256, 256>>>(Wq, pWq, n);
        n = HID * KD / 4; round_tf32_kernel<<<(n + 255) / 256, 256>>>(Wk, pWk, n);
        n = HID * KD / 4; round_tf32_kernel<<<(n + 255) / 256, 256>>>(Wv, pWv, n);
        n = QD * HID / 4; round_tf32_kernel<<<(n + 255) / 256, 256>>>(Wo, pWo, n);
    }

    cudaFuncSetAttribute(tf32gemm, cudaFuncAttributeMaxDynamicSharedMemorySize,
                         GEMM_SMEM);

    // 1. QKV projections
    tf32gemm<<<dim3(QD / 128, L / 128), 256, GEMM_SMEM>>>(pHS, pWq, pQ, L, QD, HID);
    tf32gemm<<<dim3(KD / 128, L / 128), 256, GEMM_SMEM>>>(pHS, pWk, pK, L, KD, HID);
    tf32gemm<<<dim3(KD / 128, L / 128), 256, GEMM_SMEM>>>(pHS, pWv, pV, L, KD, HID);

    // 2. RMSNorm + RoPE with hi/lo split; V hi/lo split
    norm_rope_split_kernel<<<dim3(L, NH), 256>>>(pQ, QD, qw, cosp, sinp, pQh, pQl);
    norm_rope_split_kernel<<<dim3(L, NKV), 256>>>(pK, KD, kw, cosp, sinp, pKh, pKl);
    {
        int n = L * KD / 4;
        split_tf32_kernel<<<(n + 255) / 256, 256>>>(pV, pVh, pVl, n);
    }

    // 3. attention (tensor cores, 3xTF32)
    cudaFuncSetAttribute(attn_mma_kernel,
                         cudaFuncAttributeMaxDynamicSharedMemorySize, ATT_SMEM);
    attn_mma_kernel<<<dim3(SEQ / 64, L / SEQ, NH), 256, ATT_SMEM>>>();

    // 4. output projection
    tf32gemm<<<dim3(HID / 128, L / 128), 256, GEMM_SMEM>>>(pA, pWo, out, L, HID, QD);
}